// round 2
// baseline (speedup 1.0000x reference)
#include <cuda_runtime.h>
#include <math.h>

#define HID 128
#define NEG 0.2f
#define MAXN 50000
#define MAXE 800000
#define MAXT (MAXE + MAXN)

// ---------------- static scratch (no allocations allowed) ----------------
__device__ float g_h  [MAXN * HID];
__device__ float g_xl [MAXN * HID];
__device__ float g_xr [MAXN * HID];
__device__ float g_acc[MAXN * HID];
__device__ float g_ev [(size_t)MAXT * HID];   // ~435 MB
__device__ float g_denom[MAXN];
__device__ float g_deg  [MAXN];
__device__ float g_loop [MAXN * 32];
__device__ int   g_is64;

// ---------------- small helpers ----------------
__device__ __forceinline__ void red4(float* p, float a, float b, float c, float d) {
    asm volatile("red.global.add.v4.f32 [%0], {%1,%2,%3,%4};"
                 :: "l"(p), "f"(a), "f"(b), "f"(c), "f"(d));
}
__device__ __forceinline__ void red1(float* p, float a) {
    asm volatile("red.global.add.f32 [%0], %1;" :: "l"(p), "f"(a));
}
__device__ __forceinline__ float lk(float x) { return x > 0.0f ? x : NEG * x; }

// ---------------- dtype detection for edge_index ----------------
__global__ void k_detect(const void* __restrict__ idx, int E, int N) {
    if (threadIdx.x == 0 && blockIdx.x == 0) {
        const long long* p = (const long long*)idx;
        int ok = 1;
        int cnt = 64;
        if (2 * E < 64) cnt = 2 * E;
        for (int i = 0; i < cnt; i++) {
            long long v = p[i];
            if (v < 0 || v >= (long long)N) { ok = 0; break; }
        }
        g_is64 = ok;
    }
}

// ---------------- zero (count must be multiple of 4) ----------------
__global__ void k_zero(float4* __restrict__ p, int n4) {
    int i = blockIdx.x * blockDim.x + threadIdx.x;
    if (i < n4) p[i] = make_float4(0.f, 0.f, 0.f, 0.f);
}

// ---------------- self-loop attr accumulation ----------------
__global__ void k_loopacc(const float* __restrict__ ea, const void* __restrict__ idx, int E) {
    int i = blockIdx.x * blockDim.x + threadIdx.x;   // over E*8
    if (i >= E * 8) return;
    int e = i >> 3, j = i & 7;
    int is64 = g_is64;
    int d = is64 ? (int)((const long long*)idx)[E + e] : ((const int*)idx)[E + e];
    float4 v = *(const float4*)(ea + (size_t)e * 32 + j * 4);
    red4(g_loop + (size_t)d * 32 + j * 4, v.x, v.y, v.z, v.w);
    if (j == 0) red1(g_deg + d, 1.0f);
}

__global__ void k_loopnorm(int N) {
    int i = blockIdx.x * blockDim.x + threadIdx.x;   // over N*8
    if (i >= N * 8) return;
    int node = i >> 3;
    float s = 1.0f / fmaxf(g_deg[node], 1.0f);
    float4 v = ((float4*)g_loop)[i];
    v.x *= s; v.y *= s; v.z *= s; v.w *= s;
    ((float4*)g_loop)[i] = v;
}

// ---------------- SGEMM: C[M,128] = A[M,K] @ W[K,128] (+ bias) ----------------
// 128x128 tile, BK=8, 256 threads, 8x8 register blocking.
__global__ void __launch_bounds__(256) k_gemm(const float* __restrict__ A, int K,
                                              const float* __restrict__ W,
                                              const float* __restrict__ bias,
                                              float* __restrict__ C, int M) {
    __shared__ float As[8][128];
    __shared__ float Ws[8][128];
    int tid  = threadIdx.x;
    int row0 = blockIdx.x * 128;
    int arow = tid >> 1, acol = (tid & 1) * 4;
    int wrow = tid >> 5, wcol = (tid & 31) * 4;
    int ty = tid >> 4, tx = tid & 15;

    float acc[8][8];
#pragma unroll
    for (int i = 0; i < 8; i++)
#pragma unroll
        for (int j = 0; j < 8; j++) acc[i][j] = 0.f;

    for (int k0 = 0; k0 < K; k0 += 8) {
        int r = row0 + arow;
        float4 av = (r < M) ? *(const float4*)(A + (size_t)r * K + k0 + acol)
                            : make_float4(0.f, 0.f, 0.f, 0.f);
        As[acol + 0][arow] = av.x;
        As[acol + 1][arow] = av.y;
        As[acol + 2][arow] = av.z;
        As[acol + 3][arow] = av.w;
        *(float4*)(&Ws[wrow][wcol]) = *(const float4*)(W + (size_t)(k0 + wrow) * 128 + wcol);
        __syncthreads();
#pragma unroll
        for (int kk = 0; kk < 8; kk++) {
            float a[8], b[8];
            *(float4*)(a)     = *(float4*)(&As[kk][ty * 8]);
            *(float4*)(a + 4) = *(float4*)(&As[kk][ty * 8 + 4]);
            *(float4*)(b)     = *(float4*)(&Ws[kk][tx * 8]);
            *(float4*)(b + 4) = *(float4*)(&Ws[kk][tx * 8 + 4]);
#pragma unroll
            for (int i = 0; i < 8; i++)
#pragma unroll
                for (int j = 0; j < 8; j++) acc[i][j] += a[i] * b[j];
        }
        __syncthreads();
    }

    float bv[8];
#pragma unroll
    for (int j = 0; j < 8; j++) bv[j] = bias ? bias[tx * 8 + j] : 0.f;

#pragma unroll
    for (int i = 0; i < 8; i++) {
        int r = row0 + ty * 8 + i;
        if (r < M) {
            float4 o0 = make_float4(acc[i][0] + bv[0], acc[i][1] + bv[1],
                                    acc[i][2] + bv[2], acc[i][3] + bv[3]);
            float4 o1 = make_float4(acc[i][4] + bv[4], acc[i][5] + bv[5],
                                    acc[i][6] + bv[6], acc[i][7] + bv[7]);
            *(float4*)(C + (size_t)r * 128 + tx * 8)     = o0;
            *(float4*)(C + (size_t)r * 128 + tx * 8 + 4) = o1;
        }
    }
}

// ---------------- edge pass: warp per edge ----------------
__global__ void __launch_bounds__(256) k_edge(const void* __restrict__ eidx,
                                              const float* __restrict__ att,
                                              int E, int T) {
    int wid  = (blockIdx.x * blockDim.x + threadIdx.x) >> 5;
    int lane = threadIdx.x & 31;
    if (wid >= T) return;
    int s, d;
    if (wid < E) {
        if (g_is64) {
            s = (int)((const long long*)eidx)[wid];
            d = (int)((const long long*)eidx)[E + wid];
        } else {
            s = ((const int*)eidx)[wid];
            d = ((const int*)eidx)[E + wid];
        }
    } else {
        s = d = wid - E;
    }
    int c = lane * 4;
    float4 xl = *(const float4*)(g_xl + (size_t)s * HID + c);
    float4 xr = *(const float4*)(g_xr + (size_t)d * HID + c);
    float4 ev = *(const float4*)(g_ev + (size_t)wid * HID + c);
    float4 at = *(const float4*)(att + c);

    float p = lk(xl.x + xr.x + ev.x) * at.x
            + lk(xl.y + xr.y + ev.y) * at.y
            + lk(xl.z + xr.z + ev.z) * at.z
            + lk(xl.w + xr.w + ev.w) * at.w;
#pragma unroll
    for (int o = 16; o; o >>= 1) p += __shfl_xor_sync(0xFFFFFFFFu, p, o);

    float ez = __expf(p);
    red4(g_acc + (size_t)d * HID + c, ez * xl.x, ez * xl.y, ez * xl.z, ez * xl.w);
    if (lane == 0) red1(g_denom + d, ez);
}

// ---------------- normalize + bias + silu ----------------
__global__ void k_norm(const float* __restrict__ bo, float* __restrict__ out, int N) {
    int i = blockIdx.x * blockDim.x + threadIdx.x;   // over N*32 float4s
    if (i >= N * 32) return;
    int node = i >> 5;
    int c = (i & 31) * 4;
    float inv = 1.0f / g_denom[node];
    float4 a = *(float4*)(g_acc + (size_t)node * HID + c);
    float4 b = *(const float4*)(bo + c);
    float vx = a.x * inv + b.x;
    float vy = a.y * inv + b.y;
    float vz = a.z * inv + b.z;
    float vw = a.w * inv + b.w;
    float4 o;
    o.x = vx / (1.0f + __expf(-vx));
    o.y = vy / (1.0f + __expf(-vy));
    o.z = vz / (1.0f + __expf(-vz));
    o.w = vw / (1.0f + __expf(-vw));
    *(float4*)(out + (size_t)node * HID + c) = o;
}

// ---------------- host orchestration ----------------
static inline void zero_f(float* p, int count) {          // count % 4 == 0
    int n4 = count >> 2;
    k_zero<<<(n4 + 255) / 256, 256>>>((float4*)p, n4);
}

extern "C" void kernel_launch(void* const* d_in, const int* in_sizes, int n_in,
                              void* d_out, int out_size) {
    const float* x    = (const float*)d_in[0];
    const void*  eidx = d_in[1];
    const float* ea   = (const float*)d_in[2];
    const float* W_emb = (const float*)d_in[3];
    const float* b_emb = (const float*)d_in[4];
    const float* Wl[2]  = {(const float*)d_in[5],  (const float*)d_in[11]};
    const float* bl[2]  = {(const float*)d_in[6],  (const float*)d_in[12]};
    const float* Wr[2]  = {(const float*)d_in[7],  (const float*)d_in[13]};
    const float* We[2]  = {(const float*)d_in[8],  (const float*)d_in[14]};
    const float* att[2] = {(const float*)d_in[9],  (const float*)d_in[15]};
    const float* bo[2]  = {(const float*)d_in[10], (const float*)d_in[16]};

    int N = in_sizes[0] / HID;
    int E = in_sizes[2] / 32;
    int T = E + N;

    float *p_h, *p_xl, *p_xr, *p_acc, *p_ev, *p_denom, *p_deg, *p_loop;
    cudaGetSymbolAddress((void**)&p_h,     g_h);
    cudaGetSymbolAddress((void**)&p_xl,    g_xl);
    cudaGetSymbolAddress((void**)&p_xr,    g_xr);
    cudaGetSymbolAddress((void**)&p_acc,   g_acc);
    cudaGetSymbolAddress((void**)&p_ev,    g_ev);
    cudaGetSymbolAddress((void**)&p_denom, g_denom);
    cudaGetSymbolAddress((void**)&p_deg,   g_deg);
    cudaGetSymbolAddress((void**)&p_loop,  g_loop);

    k_detect<<<1, 1>>>(eidx, E, N);

    // self-loop attr (layer-independent)
    zero_f(p_deg, N);
    zero_f(p_loop, N * 32);
    k_loopacc<<<(E * 8 + 255) / 256, 256>>>(ea, eidx, E);
    k_loopnorm<<<(N * 8 + 255) / 256, 256>>>(N);

    // embedding
    int gb_n = (N + 127) / 128;
    k_gemm<<<gb_n, 256>>>(x, HID, W_emb, b_emb, p_h, N);

    for (int l = 0; l < 2; l++) {
        k_gemm<<<gb_n, 256>>>(p_h, HID, Wl[l], bl[l], p_xl, N);
        k_gemm<<<gb_n, 256>>>(p_h, HID, Wr[l], nullptr, p_xr, N);
        k_gemm<<<(E + 127) / 128, 256>>>(ea, 32, We[l], nullptr, p_ev, E);
        k_gemm<<<gb_n, 256>>>(p_loop, 32, We[l], nullptr, p_ev + (size_t)E * HID, N);

        zero_f(p_acc, N * HID);
        zero_f(p_denom, N);
        k_edge<<<((long long)T * 32 + 255) / 256, 256>>>(eidx, att[l], E, T);

        float* dst = (l == 0) ? p_h : (float*)d_out;
        k_norm<<<(N * 32 + 255) / 256, 256>>>(bo[l], dst, N);
    }
}

// round 3
// speedup vs baseline: 1.0423x; 1.0423x over previous
#include <cuda_runtime.h>
#include <math.h>

#define HID 128
#define NEG 0.2f
#define MAXN 50000
#define MAXE 800000
#define MAXT (MAXE + MAXN)

// ---------------- static scratch (no allocations allowed) ----------------
__device__ float g_h  [MAXN * HID];
__device__ float g_xl [MAXN * HID];
__device__ float g_xr [MAXN * HID];
__device__ float g_acc[MAXN * HID];
__device__ float g_ev [(size_t)MAXT * HID];   // ~435 MB
__device__ float g_denom[MAXN];
__device__ float g_deg  [MAXN];
__device__ float g_loop [MAXN * 32];
__device__ int   g_is64;

// ---------------- small helpers ----------------
__device__ __forceinline__ void red4(float* p, float a, float b, float c, float d) {
    asm volatile("red.global.add.v4.f32 [%0], {%1,%2,%3,%4};"
                 :: "l"(p), "f"(a), "f"(b), "f"(c), "f"(d));
}
__device__ __forceinline__ void red1(float* p, float a) {
    asm volatile("red.global.add.f32 [%0], %1;" :: "l"(p), "f"(a));
}
__device__ __forceinline__ float lk(float x) { return x > 0.0f ? x : NEG * x; }

__device__ __forceinline__ unsigned long long pk2(float x, float y) {
    unsigned long long r;
    asm("mov.b64 %0, {%1, %2};" : "=l"(r) : "f"(x), "f"(y));
    return r;
}
__device__ __forceinline__ void fma2(unsigned long long& d,
                                     unsigned long long a, unsigned long long b) {
    asm("fma.rn.f32x2 %0, %1, %2, %0;" : "+l"(d) : "l"(a), "l"(b));
}
__device__ __forceinline__ float2 up2(unsigned long long v) {
    float2 r;
    asm("mov.b64 {%0, %1}, %2;" : "=f"(r.x), "=f"(r.y) : "l"(v));
    return r;
}

// ---------------- dtype detection for edge_index ----------------
__global__ void k_detect(const void* __restrict__ idx, int E, int N) {
    if (threadIdx.x == 0 && blockIdx.x == 0) {
        const long long* p = (const long long*)idx;
        int ok = 1;
        int cnt = 64;
        if (2 * E < 64) cnt = 2 * E;
        for (int i = 0; i < cnt; i++) {
            long long v = p[i];
            if (v < 0 || v >= (long long)N) { ok = 0; break; }
        }
        g_is64 = ok;
    }
}

// ---------------- zero (count must be multiple of 4) ----------------
__global__ void k_zero(float4* __restrict__ p, int n4) {
    int i = blockIdx.x * blockDim.x + threadIdx.x;
    if (i < n4) p[i] = make_float4(0.f, 0.f, 0.f, 0.f);
}

// ---------------- self-loop attr accumulation ----------------
__global__ void k_loopacc(const float* __restrict__ ea, const void* __restrict__ idx, int E) {
    int i = blockIdx.x * blockDim.x + threadIdx.x;   // over E*8
    if (i >= E * 8) return;
    int e = i >> 3, j = i & 7;
    int is64 = g_is64;
    int d = is64 ? (int)((const long long*)idx)[E + e] : ((const int*)idx)[E + e];
    float4 v = *(const float4*)(ea + (size_t)e * 32 + j * 4);
    red4(g_loop + (size_t)d * 32 + j * 4, v.x, v.y, v.z, v.w);
    if (j == 0) red1(g_deg + d, 1.0f);
}

__global__ void k_loopnorm(int N) {
    int i = blockIdx.x * blockDim.x + threadIdx.x;   // over N*8
    if (i >= N * 8) return;
    int node = i >> 3;
    float s = 1.0f / fmaxf(g_deg[node], 1.0f);
    float4 v = ((float4*)g_loop)[i];
    v.x *= s; v.y *= s; v.z *= s; v.w *= s;
    ((float4*)g_loop)[i] = v;
}

// ---------------- SGEMM: C[M,128] = A[M,K] @ W[K,128] (+ bias) ----------------
// 128x128 tile, BK=8, 256 threads, 8x8 register blocking, packed f32x2 FMA.
__global__ void __launch_bounds__(256) k_gemm(const float* __restrict__ A, int K,
                                              const float* __restrict__ W,
                                              const float* __restrict__ bias,
                                              float* __restrict__ C, int M) {
    __shared__ float As[8][128];
    __shared__ float Ws[8][128];
    int tid  = threadIdx.x;
    int row0 = blockIdx.x * 128;
    int arow = tid >> 1, acol = (tid & 1) * 4;
    int wrow = tid >> 5, wcol = (tid & 31) * 4;
    int ty = tid >> 4, tx = tid & 15;

    // packed accumulators: acc2[i][j] holds cols (tx*8+2j, tx*8+2j+1) for row ty*8+i
    unsigned long long acc2[8][4];
#pragma unroll
    for (int i = 0; i < 8; i++)
#pragma unroll
        for (int j = 0; j < 4; j++) acc2[i][j] = 0ULL;

    for (int k0 = 0; k0 < K; k0 += 8) {
        int r = row0 + arow;
        float4 av = (r < M) ? *(const float4*)(A + (size_t)r * K + k0 + acol)
                            : make_float4(0.f, 0.f, 0.f, 0.f);
        As[acol + 0][arow] = av.x;
        As[acol + 1][arow] = av.y;
        As[acol + 2][arow] = av.z;
        As[acol + 3][arow] = av.w;
        *(float4*)(&Ws[wrow][wcol]) = *(const float4*)(W + (size_t)(k0 + wrow) * 128 + wcol);
        __syncthreads();
#pragma unroll
        for (int kk = 0; kk < 8; kk++) {
            float a[8];
            unsigned long long b2[4];
            *(float4*)(a)     = *(float4*)(&As[kk][ty * 8]);
            *(float4*)(a + 4) = *(float4*)(&As[kk][ty * 8 + 4]);
            const unsigned long long* wp =
                (const unsigned long long*)(&Ws[kk][tx * 8]);
            b2[0] = wp[0]; b2[1] = wp[1]; b2[2] = wp[2]; b2[3] = wp[3];
#pragma unroll
            for (int i = 0; i < 8; i++) {
                unsigned long long pa = pk2(a[i], a[i]);
#pragma unroll
                for (int j = 0; j < 4; j++) fma2(acc2[i][j], pa, b2[j]);
            }
        }
        __syncthreads();
    }

    float bv[8];
#pragma unroll
    for (int j = 0; j < 8; j++) bv[j] = bias ? bias[tx * 8 + j] : 0.f;

#pragma unroll
    for (int i = 0; i < 8; i++) {
        int r = row0 + ty * 8 + i;
        if (r < M) {
            float2 p0 = up2(acc2[i][0]);
            float2 p1 = up2(acc2[i][1]);
            float2 p2 = up2(acc2[i][2]);
            float2 p3 = up2(acc2[i][3]);
            float4 o0 = make_float4(p0.x + bv[0], p0.y + bv[1],
                                    p1.x + bv[2], p1.y + bv[3]);
            float4 o1 = make_float4(p2.x + bv[4], p2.y + bv[5],
                                    p3.x + bv[6], p3.y + bv[7]);
            *(float4*)(C + (size_t)r * 128 + tx * 8)     = o0;
            *(float4*)(C + (size_t)r * 128 + tx * 8 + 4) = o1;
        }
    }
}

// ---------------- edge pass: warp per edge ----------------
__global__ void __launch_bounds__(256) k_edge(const void* __restrict__ eidx,
                                              const float* __restrict__ att,
                                              int E, int T) {
    int wid  = (blockIdx.x * blockDim.x + threadIdx.x) >> 5;
    int lane = threadIdx.x & 31;
    if (wid >= T) return;
    int s, d;
    if (wid < E) {
        if (g_is64) {
            s = (int)((const long long*)eidx)[wid];
            d = (int)((const long long*)eidx)[E + wid];
        } else {
            s = ((const int*)eidx)[wid];
            d = ((const int*)eidx)[E + wid];
        }
    } else {
        s = d = wid - E;
    }
    int c = lane * 4;
    float4 xl = *(const float4*)(g_xl + (size_t)s * HID + c);
    float4 xr = *(const float4*)(g_xr + (size_t)d * HID + c);
    float4 ev = *(const float4*)(g_ev + (size_t)wid * HID + c);
    float4 at = *(const float4*)(att + c);

    float p = lk(xl.x + xr.x + ev.x) * at.x
            + lk(xl.y + xr.y + ev.y) * at.y
            + lk(xl.z + xr.z + ev.z) * at.z
            + lk(xl.w + xr.w + ev.w) * at.w;
#pragma unroll
    for (int o = 16; o; o >>= 1) p += __shfl_xor_sync(0xFFFFFFFFu, p, o);

    float ez = __expf(p);
    red4(g_acc + (size_t)d * HID + c, ez * xl.x, ez * xl.y, ez * xl.z, ez * xl.w);
    if (lane == 0) red1(g_denom + d, ez);
}

// ---------------- normalize + bias + silu ----------------
__global__ void k_norm(const float* __restrict__ bo, float* __restrict__ out, int N) {
    int i = blockIdx.x * blockDim.x + threadIdx.x;   // over N*32 float4s
    if (i >= N * 32) return;
    int node = i >> 5;
    int c = (i & 31) * 4;
    float inv = 1.0f / g_denom[node];
    float4 a = *(float4*)(g_acc + (size_t)node * HID + c);
    float4 b = *(const float4*)(bo + c);
    float vx = a.x * inv + b.x;
    float vy = a.y * inv + b.y;
    float vz = a.z * inv + b.z;
    float vw = a.w * inv + b.w;
    float4 o;
    o.x = vx / (1.0f + __expf(-vx));
    o.y = vy / (1.0f + __expf(-vy));
    o.z = vz / (1.0f + __expf(-vz));
    o.w = vw / (1.0f + __expf(-vw));
    *(float4*)(out + (size_t)node * HID + c) = o;
}

// ---------------- host orchestration ----------------
static inline void zero_f(float* p, int count) {          // count % 4 == 0
    int n4 = count >> 2;
    k_zero<<<(n4 + 255) / 256, 256>>>((float4*)p, n4);
}

extern "C" void kernel_launch(void* const* d_in, const int* in_sizes, int n_in,
                              void* d_out, int out_size) {
    const float* x    = (const float*)d_in[0];
    const void*  eidx = d_in[1];
    const float* ea   = (const float*)d_in[2];
    const float* W_emb = (const float*)d_in[3];
    const float* b_emb = (const float*)d_in[4];
    const float* Wl[2]  = {(const float*)d_in[5],  (const float*)d_in[11]};
    const float* bl[2]  = {(const float*)d_in[6],  (const float*)d_in[12]};
    const float* Wr[2]  = {(const float*)d_in[7],  (const float*)d_in[13]};
    const float* We[2]  = {(const float*)d_in[8],  (const float*)d_in[14]};
    const float* att[2] = {(const float*)d_in[9],  (const float*)d_in[15]};
    const float* bo[2]  = {(const float*)d_in[10], (const float*)d_in[16]};

    int N = in_sizes[0] / HID;
    int E = in_sizes[2] / 32;
    int T = E + N;

    float *p_h, *p_xl, *p_xr, *p_acc, *p_ev, *p_denom, *p_deg, *p_loop;
    cudaGetSymbolAddress((void**)&p_h,     g_h);
    cudaGetSymbolAddress((void**)&p_xl,    g_xl);
    cudaGetSymbolAddress((void**)&p_xr,    g_xr);
    cudaGetSymbolAddress((void**)&p_acc,   g_acc);
    cudaGetSymbolAddress((void**)&p_ev,    g_ev);
    cudaGetSymbolAddress((void**)&p_denom, g_denom);
    cudaGetSymbolAddress((void**)&p_deg,   g_deg);
    cudaGetSymbolAddress((void**)&p_loop,  g_loop);

    k_detect<<<1, 1>>>(eidx, E, N);

    // self-loop attr (layer-independent)
    zero_f(p_deg, N);
    zero_f(p_loop, N * 32);
    k_loopacc<<<(E * 8 + 255) / 256, 256>>>(ea, eidx, E);
    k_loopnorm<<<(N * 8 + 255) / 256, 256>>>(N);

    // embedding
    int gb_n = (N + 127) / 128;
    k_gemm<<<gb_n, 256>>>(x, HID, W_emb, b_emb, p_h, N);

    for (int l = 0; l < 2; l++) {
        k_gemm<<<gb_n, 256>>>(p_h, HID, Wl[l], bl[l], p_xl, N);
        k_gemm<<<gb_n, 256>>>(p_h, HID, Wr[l], nullptr, p_xr, N);
        k_gemm<<<(E + 127) / 128, 256>>>(ea, 32, We[l], nullptr, p_ev, E);
        k_gemm<<<gb_n, 256>>>(p_loop, 32, We[l], nullptr, p_ev + (size_t)E * HID, N);

        zero_f(p_acc, N * HID);
        zero_f(p_denom, N);
        k_edge<<<((long long)T * 32 + 255) / 256, 256>>>(eidx, att[l], E, T);

        float* dst = (l == 0) ? p_h : (float*)d_out;
        k_norm<<<(N * 32 + 255) / 256, 256>>>(bo[l], dst, N);
    }
}